// round 8
// baseline (speedup 1.0000x reference)
#include <cuda_runtime.h>
#include <cstdint>

// ---------------------------------------------------------------------------
// Net_17188459119113 — R8: single persistent kernel, x retained in smem.
// 4-bit quant conv(1->16,3x3) + bias + relu + maxpool(4) + 4-bit quant FC.
// Integer-code dp4a math (exact); scales applied once at the end.
//
// 512 blocks x 288 threads, 49KB dyn smem (16 images of x per block).
//   Phase A: bulk-async copy 16 images -> smem; blocks 0/1 quantize weights
//            while waiting; amax from smem -> g_xpart[bid].
//   Phase B: conv+pool from smem patches (x never re-read from global);
//            flat (b,j,c) layout; g_fpart[bid].
//   Phase C: fc GEMV, 2 rows/warp, fc packs overlaid on x smem region.
// Co-residency: 4 CTAs/SM by smem (592 slots >= 512); launch_bounds(288,4)
// gives 56 regs (no spills). Sense-reversing barrier self-resets per replay.
// ---------------------------------------------------------------------------

#define BATCH     8192
#define IN_PIX    784
#define FLAT_DIM  576
#define FC_GROUPS 144
#define NB        512
#define IMG_PER_BLK 16
#define SMX_FLOATS (IMG_PER_BLK * IN_PIX)   // 12544
#define SMX_BYTES  (SMX_FLOATS * 4)         // 50176
#define SMX_F4     (SMX_FLOATS / 4)         // 3136

__device__ float        g_flat[BATCH * FLAT_DIM];   // (b, j, c) layout
__device__ unsigned int g_xpart[NB];
__device__ unsigned int g_fpart[NB];
__device__ int          g_convw_pack[48];
__device__ int          g_fcw_pack[10 * FC_GROUPS];
__device__ float        g_sw_conv;
__device__ float        g_sw_fc;
__device__ unsigned int g_cnt;      // barrier arrivals (self-resetting)
__device__ unsigned int g_sense;    // barrier sense (2 flips per replay)

__device__ __forceinline__ int qcode(float v, float inv_s) {
    return __float2int_rn(fminf(fmaxf(v * inv_s, -7.0f), 7.0f));
}
__device__ __forceinline__ unsigned pack4(int a, int b, int c, int d) {
    return (unsigned)((a & 0xff) | ((b & 0xff) << 8) | ((c & 0xff) << 16) | (d << 24));
}

__device__ __forceinline__ unsigned block_umax(unsigned m, unsigned* sm) {
    __syncthreads();                 // protect sm reuse across calls
    if (threadIdx.x == 0) *sm = 0u;
    __syncthreads();
    m = __reduce_max_sync(0xFFFFFFFFu, m);
    if ((threadIdx.x & 31) == 0) atomicMax(sm, m);
    __syncthreads();
    return *sm;
}

// Sense-reversing grid barrier; all NB blocks co-resident.
__device__ __forceinline__ void grid_barrier(unsigned wait_sense) {
    __syncthreads();
    if (threadIdx.x == 0) {
        __threadfence();
        unsigned old = atomicAdd(&g_cnt, 1u);
        if (old == NB - 1u) {
            g_cnt = 0u;
            __threadfence();
            atomicExch(&g_sense, wait_sense ^ 1u);
        } else {
            while (*(volatile unsigned*)&g_sense == wait_sense)
                __nanosleep(32);
        }
        __threadfence();
    }
    __syncthreads();
}

// ---- mbarrier + bulk-async helpers -----------------------------------------
__device__ __forceinline__ void mbar_init(uint32_t a, uint32_t cnt) {
    asm volatile("mbarrier.init.shared.b64 [%0], %1;" :: "r"(a), "r"(cnt) : "memory");
}
__device__ __forceinline__ void mbar_expect_tx(uint32_t a, uint32_t bytes) {
    asm volatile("mbarrier.arrive.expect_tx.shared.b64 _, [%0], %1;"
                 :: "r"(a), "r"(bytes) : "memory");
}
__device__ __forceinline__ void bulk_g2s(uint32_t dst, const void* src,
                                         uint32_t bytes, uint32_t mbar) {
    asm volatile(
        "cp.async.bulk.shared::cta.global.mbarrier::complete_tx::bytes "
        "[%0], [%1], %2, [%3];"
        :: "r"(dst), "l"(src), "r"(bytes), "r"(mbar) : "memory");
}
__device__ __forceinline__ void mbar_wait_parity0(uint32_t a) {
    asm volatile(
        "{\n\t"
        ".reg .pred p;\n\t"
        "WAIT_%=:\n\t"
        "mbarrier.try_wait.parity.acquire.cta.shared::cta.b64 p, [%0], 0;\n\t"
        "@!p bra WAIT_%=;\n\t"
        "}"
        :: "r"(a) : "memory");
}

__global__ void __launch_bounds__(288, 4)
k_fused(const float* __restrict__ x,
        const float*  __restrict__ conv_w, const float* __restrict__ conv_b,
        const float*  __restrict__ fc_w,   const float* __restrict__ fc_b,
        float* __restrict__ out) {
    extern __shared__ __align__(128) float smx[];   // 16 images of x (49KB)
    __shared__ unsigned long long mbar;
    __shared__ unsigned sm;
    __shared__ int      swp[48];
    __shared__ float    sb16[16];
    __shared__ float    sbias[10];

    const int tid = threadIdx.x;
    const int bid = blockIdx.x;
    const unsigned sense0 = *(volatile unsigned*)&g_sense;   // pre-arrival read

    // ======================= Phase A ========================================
    uint32_t mb   = (uint32_t)__cvta_generic_to_shared(&mbar);
    uint32_t sbuf = (uint32_t)__cvta_generic_to_shared(smx);

    if (tid == 0) mbar_init(mb, 1);
    __syncthreads();
    if (tid == 0) {
        mbar_expect_tx(mb, SMX_BYTES);
        bulk_g2s(sbuf, x + (size_t)bid * SMX_FLOATS, SMX_BYTES, mb);
    }

    // overlap the copy-wait with weight quantization
    if (bid == 0) {
        unsigned wm = (tid < 144) ? __float_as_uint(fabsf(conv_w[tid])) : 0u;
        wm = block_umax(wm, &sm);
        float s_cw = __uint_as_float(wm) / 7.0f + 1e-8f;
        if (tid == 0) g_sw_conv = s_cw;
        float inv_cw = 1.0f / s_cw;
        if (tid < 48) {
            const float* wr = conv_w + tid * 3;
            g_convw_pack[tid] = (int)pack4(qcode(wr[0], inv_cw),
                                           qcode(wr[1], inv_cw),
                                           qcode(wr[2], inv_cw), 0);
        }
    } else if (bid == 1) {
        unsigned wm = 0u;
        for (int i = tid; i < 5760; i += 288)
            wm = max(wm, __float_as_uint(fabsf(fc_w[i])));
        wm = block_umax(wm, &sm);
        float s_fw = __uint_as_float(wm) / 7.0f + 1e-8f;
        if (tid == 0) g_sw_fc = s_fw;
        float inv_fw = 1.0f / s_fw;
        // permuted: group g covers new-k = 4g..4g+3, new-k = j*16+c,
        // original flat index = c*36 + j
        for (int i = tid; i < 10 * FC_GROUPS; i += 288) {
            int o = i / FC_GROUPS, g = i % FC_GROUPS;
            int b4[4];
            #pragma unroll
            for (int t = 0; t < 4; t++) {
                int nk = 4 * g + t;
                int j = nk >> 4, c = nk & 15;
                b4[t] = qcode(fc_w[o * FLAT_DIM + c * 36 + j], inv_fw);
            }
            g_fcw_pack[i] = (int)pack4(b4[0], b4[1], b4[2], b4[3]);
        }
    }

    mbar_wait_parity0(mb);

    // amax of this block's slice from smem
    {
        unsigned m = 0u;
        const float4* s4 = (const float4*)smx;
        #pragma unroll
        for (int i = 0; i < 11; i++) {
            int idx = tid + i * 288;
            if (idx < SMX_F4) {
                float4 v = s4[idx];
                m = max(m, __float_as_uint(fabsf(v.x)));
                m = max(m, __float_as_uint(fabsf(v.y)));
                m = max(m, __float_as_uint(fabsf(v.z)));
                m = max(m, __float_as_uint(fabsf(v.w)));
            }
        }
        m = block_umax(m, &sm);
        if (tid == 0) g_xpart[bid] = m;
    }

    grid_barrier(sense0);

    // ======================= Phase B: conv+pool from smem ===================
    {
        unsigned m = 0u;
        for (int i = tid; i < NB; i += 288) m = max(m, g_xpart[i]);
        unsigned xbits = block_umax(m, &sm);

        if (tid < 48) swp[tid] = g_convw_pack[tid];
        if (tid < 16) sb16[tid] = conv_b[tid];
        __syncthreads();

        float s_x   = __uint_as_float(xbits) / 7.0f + 1e-8f;
        float inv_s = 1.0f / s_x;
        float sprod = s_x * g_sw_conv;

        unsigned lmax = 0u;

        #pragma unroll 1
        for (int pp = 0; pp < 2; pp++) {
            int p   = tid + pp * 288;           // 0..575
            int img = p / 36;
            int pos = p % 36;
            int ph = pos / 6, pw = pos % 6;

            const float* ip = smx + img * IN_PIX + (4 * ph) * 28 + 4 * pw;

            unsigned win[24];
            #pragma unroll
            for (int r = 0; r < 6; r++) {
                float4 v4 = *(const float4*)(ip + r * 28);
                float2 v2 = *(const float2*)(ip + r * 28 + 4);
                unsigned p0 = pack4(qcode(v4.x, inv_s), qcode(v4.y, inv_s),
                                    qcode(v4.z, inv_s), qcode(v4.w, inv_s));
                unsigned p1 = pack4(qcode(v2.x, inv_s), qcode(v2.y, inv_s), 0, 0);
                win[r * 4 + 0] = p0;
                win[r * 4 + 1] = __funnelshift_r(p0, p1, 8);
                win[r * 4 + 2] = __funnelshift_r(p0, p1, 16);
                win[r * 4 + 3] = __funnelshift_r(p0, p1, 24);
            }

            int b = bid * IMG_PER_BLK + img;
            float* fout = g_flat + b * FLAT_DIM + pos * 16;

            #pragma unroll 1
            for (int cg = 0; cg < 4; cg++) {
                float ych[4];
                #pragma unroll
                for (int cc = 0; cc < 4; cc++) {
                    int c = cg * 4 + cc;
                    int w0 = swp[c * 3 + 0];
                    int w1 = swp[c * 3 + 1];
                    int w2 = swp[c * 3 + 2];

                    int mx = -(1 << 30);
                    #pragma unroll
                    for (int i = 0; i < 4; i++) {
                        #pragma unroll
                        for (int j = 0; j < 4; j++) {
                            int acc = __dp4a((int)win[i * 4 + j],       w0, 0);
                            acc     = __dp4a((int)win[(i + 1) * 4 + j], w1, acc);
                            acc     = __dp4a((int)win[(i + 2) * 4 + j], w2, acc);
                            mx = max(mx, acc);
                        }
                    }
                    float y = fmaxf(fmaf((float)mx, sprod, sb16[c]), 0.0f);
                    ych[cc] = y;
                    lmax = max(lmax, __float_as_uint(y));
                }
                *(float4*)(fout + cg * 4) =
                    make_float4(ych[0], ych[1], ych[2], ych[3]);
            }
        }

        lmax = block_umax(lmax, &sm);
        if (tid == 0) g_fpart[bid] = lmax;
    }

    grid_barrier(sense0 ^ 1u);

    // ======================= Phase C: FC =====================================
    {
        unsigned m = 0u;
        for (int i = tid; i < NB; i += 288) m = max(m, g_fpart[i]);
        unsigned fbits = block_umax(m, &sm);

        int* swq = (int*)smx;    // overlay fc packs on the x region
        for (int i = tid; i < 10 * FC_GROUPS; i += 288)
            swq[i] = g_fcw_pack[i];
        if (tid < 10) sbias[tid] = fc_b[tid];
        __syncthreads();

        if (tid >= 256) return;   // warp 8 idle past this point

        float s_f   = __uint_as_float(fbits) / 7.0f + 1e-8f;
        float inv_s = 1.0f / s_f;
        float sprod = s_f * g_sw_fc;

        int warp = tid >> 5;
        int lane = tid & 31;
        int b0 = (bid * 8 + warp) * 2;

        const float4* fr0 = (const float4*)(g_flat + b0 * FLAT_DIM);
        const float4* fr1 = (const float4*)(g_flat + (b0 + 1) * FLAT_DIM);

        int acc0[10], acc1[10];
        #pragma unroll
        for (int o = 0; o < 10; o++) { acc0[o] = 0; acc1[o] = 0; }

        #pragma unroll
        for (int it = 0; it < 5; it++) {
            int g = lane + it * 32;
            if (g < FC_GROUPS) {
                float4 v0 = fr0[g];
                float4 v1 = fr1[g];
                int p0 = (int)pack4(
                    __float2int_rn(fminf(v0.x * inv_s, 7.0f)),
                    __float2int_rn(fminf(v0.y * inv_s, 7.0f)),
                    __float2int_rn(fminf(v0.z * inv_s, 7.0f)),
                    __float2int_rn(fminf(v0.w * inv_s, 7.0f)));
                int p1 = (int)pack4(
                    __float2int_rn(fminf(v1.x * inv_s, 7.0f)),
                    __float2int_rn(fminf(v1.y * inv_s, 7.0f)),
                    __float2int_rn(fminf(v1.z * inv_s, 7.0f)),
                    __float2int_rn(fminf(v1.w * inv_s, 7.0f)));
                #pragma unroll
                for (int o = 0; o < 10; o++) {
                    int w = swq[o * FC_GROUPS + g];
                    acc0[o] = __dp4a(p0, w, acc0[o]);
                    acc1[o] = __dp4a(p1, w, acc1[o]);
                }
            }
        }

        #pragma unroll
        for (int o = 0; o < 10; o++) {
            acc0[o] = __reduce_add_sync(0xFFFFFFFFu, acc0[o]);
            acc1[o] = __reduce_add_sync(0xFFFFFFFFu, acc1[o]);
        }

        if (lane < 10)
            out[b0 * 10 + lane] = fmaf((float)acc0[lane], sprod, sbias[lane]);
        else if (lane >= 16 && lane < 26)
            out[(b0 + 1) * 10 + (lane - 16)] =
                fmaf((float)acc1[lane - 16], sprod, sbias[lane - 16]);
    }
}

// ---------------------------------------------------------------------------
// kernel_launch — one persistent kernel, graph-capturable.
// ---------------------------------------------------------------------------
extern "C" void kernel_launch(void* const* d_in, const int* in_sizes, int n_in,
                              void* d_out, int out_size) {
    const float* x      = (const float*)d_in[0];
    const float* conv_w = (const float*)d_in[1];
    const float* conv_b = (const float*)d_in[2];
    const float* fc_w   = (const float*)d_in[3];
    const float* fc_b   = (const float*)d_in[4];
    float* out = (float*)d_out;

    static int smem_set = 0;
    if (!smem_set) {
        cudaFuncSetAttribute(k_fused,
                             cudaFuncAttributeMaxDynamicSharedMemorySize,
                             SMX_BYTES);
        smem_set = 1;
    }

    k_fused<<<NB, 288, SMX_BYTES>>>(x, conv_w, conv_b, fc_w, fc_b, out);
}

// round 9
// speedup vs baseline: 1.2310x; 1.2310x over previous
#include <cuda_runtime.h>
#include <cstdint>

// ---------------------------------------------------------------------------
// Net_17188459119113 — R9: R7 structure, amax via 256-bit loads.
// 4-bit quant conv(1->16,3x3) + bias + relu + maxpool(4) + 4-bit quant FC.
// Integer-code dp4a math (exact), scales applied at the end.
//
//   k_amax : blocks 0..783 scan a contiguous 32KB chunk of x with
//            ld.global.nc.v4.u64 (LDG.256) — 4 x 32B per thread — testing
//            whether the ~2.2TB/s wall is a per-transaction cap;
//            block 784 quantizes+packs both weight tensors.
//   k_conv : PDL-gated; dp4a conv+pool; flat (b,j,c) layout; g_fpart[].
//   k_fc   : PDL-gated; 2 rows/warp dp4a GEMV.
// ---------------------------------------------------------------------------

#define BATCH     8192
#define IN_HW     28
#define IN_PIX    784
#define FLAT_DIM  576
#define FC_GROUPS 144
#define XBLOCKS   784                 // 784 * 32KB == 25690112 B == |x| exactly
#define CONVBLOCKS 1152
#define FCBLOCKS  512

__device__ float        g_flat[BATCH * FLAT_DIM];     // (b, j, c) layout
__device__ unsigned int g_xpart[XBLOCKS + 1];
__device__ unsigned int g_fpart[CONVBLOCKS];
__device__ int          g_convw_pack[48];             // [c][row]: bytes [w0,w1,w2,0]
__device__ int          g_fcw_pack[10 * FC_GROUPS];   // permuted (j,c) packing
__device__ float        g_sw_conv;
__device__ float        g_sw_fc;

__device__ __forceinline__ int qcode(float v, float inv_s) {
    return __float2int_rn(fminf(fmaxf(v * inv_s, -7.0f), 7.0f));
}
__device__ __forceinline__ unsigned pack4(int a, int b, int c, int d) {
    return (unsigned)((a & 0xff) | ((b & 0xff) << 8) | ((c & 0xff) << 16) | (d << 24));
}

__device__ __forceinline__ unsigned block_umax(unsigned m, unsigned* sm) {
    if (threadIdx.x == 0) *sm = 0u;
    __syncthreads();
    m = __reduce_max_sync(0xFFFFFFFFu, m);
    if ((threadIdx.x & 31) == 0) atomicMax(sm, m);
    __syncthreads();
    return *sm;
}

// 32-byte global load (sm_100+ 256-bit LDG), non-coherent path.
__device__ __forceinline__ void ldg256(const void* p,
                                       unsigned long long& a, unsigned long long& b,
                                       unsigned long long& c, unsigned long long& d) {
    asm volatile("ld.global.nc.v4.u64 {%0,%1,%2,%3}, [%4];"
                 : "=l"(a), "=l"(b), "=l"(c), "=l"(d) : "l"(p));
}

// ---------------------------------------------------------------------------
// k_amax: 256-bit-load abs-max partials + weight quant block (block 784).
// ---------------------------------------------------------------------------
__global__ void __launch_bounds__(256)
k_amax(const float* __restrict__ x,
       const float* __restrict__ conv_w, const float* __restrict__ fc_w) {
    __shared__ unsigned sm;

    if (blockIdx.x == XBLOCKS) {
        unsigned m = 0u;
        for (int i = threadIdx.x; i < 144; i += 256)
            m = max(m, __float_as_uint(fabsf(conv_w[i])));
        unsigned cw_bits = block_umax(m, &sm);
        __syncthreads();
        m = 0u;
        for (int i = threadIdx.x; i < 5760; i += 256)
            m = max(m, __float_as_uint(fabsf(fc_w[i])));
        unsigned fw_bits = block_umax(m, &sm);

        float s_cw = __uint_as_float(cw_bits) / 7.0f + 1e-8f;
        float s_fw = __uint_as_float(fw_bits) / 7.0f + 1e-8f;
        if (threadIdx.x == 0) {
            g_sw_conv = s_cw;
            g_sw_fc   = s_fw;
            g_xpart[XBLOCKS] = 0u;
        }
        float inv_cw = 1.0f / s_cw;
        float inv_fw = 1.0f / s_fw;

        for (int i = threadIdx.x; i < 48; i += 256) {
            const float* wr = conv_w + i * 3;
            g_convw_pack[i] = (int)pack4(qcode(wr[0], inv_cw),
                                         qcode(wr[1], inv_cw),
                                         qcode(wr[2], inv_cw), 0);
        }
        // fc permuted: group g covers new-k = 4g..4g+3, new-k = j*16+c,
        // original flat index = c*36 + j
        for (int i = threadIdx.x; i < 10 * FC_GROUPS; i += 256) {
            int o = i / FC_GROUPS, g = i % FC_GROUPS;
            int b4[4];
            #pragma unroll
            for (int t = 0; t < 4; t++) {
                int nk = 4 * g + t;
                int j = nk >> 4, c = nk & 15;
                b4[t] = qcode(fc_w[o * FLAT_DIM + c * 36 + j], inv_fw);
            }
            g_fcw_pack[i] = (int)pack4(b4[0], b4[1], b4[2], b4[3]);
        }
        cudaTriggerProgrammaticLaunchCompletion();
        return;
    }

    // ---- x scan: 4 x 32B loads per thread, warp-contiguous 1KB/instr ----
    const unsigned long long SMASK = 0x7FFFFFFF7FFFFFFFull;
    const char* base = (const char*)x + (size_t)blockIdx.x * 32768;
    unsigned m = 0u;
    #pragma unroll
    for (int k = 0; k < 4; k++) {
        unsigned long long a, b, c, d;
        ldg256(base + (k * 256 + threadIdx.x) * 32, a, b, c, d);
        a &= SMASK; b &= SMASK; c &= SMASK; d &= SMASK;
        unsigned long long ab = max(a, b) | max(c, d);   // NOT valid for packed!
        (void)ab;
        m = max(m, (unsigned)a);  m = max(m, (unsigned)(a >> 32));
        m = max(m, (unsigned)b);  m = max(m, (unsigned)(b >> 32));
        m = max(m, (unsigned)c);  m = max(m, (unsigned)(c >> 32));
        m = max(m, (unsigned)d);  m = max(m, (unsigned)(d >> 32));
    }
    m = block_umax(m, &sm);
    if (threadIdx.x == 0) g_xpart[blockIdx.x] = m;
    cudaTriggerProgrammaticLaunchCompletion();
}

// ---------------------------------------------------------------------------
// k_conv: PDL-gated. dp4a conv+pool, (j,c)-layout flat, partial flat max.
// ---------------------------------------------------------------------------
__global__ void __launch_bounds__(256)
k_conv(const float* __restrict__ x, const float* __restrict__ conv_b) {
    __shared__ int      swp[48];
    __shared__ float    sb[16];
    __shared__ unsigned sm;

    int idx = blockIdx.x * 256 + threadIdx.x;
    int pw = idx % 6;
    int t  = idx / 6;
    int ph = t % 6;
    int b  = t / 6;

    cudaGridDependencySynchronize();

    unsigned m = 0u;
    for (int i = threadIdx.x; i <= XBLOCKS; i += 256) m = max(m, g_xpart[i]);
    unsigned xbits = block_umax(m, &sm);

    if (threadIdx.x < 48) swp[threadIdx.x] = g_convw_pack[threadIdx.x];
    if (threadIdx.x < 16) sb[threadIdx.x]  = conv_b[threadIdx.x];
    __syncthreads();

    float s_x   = __uint_as_float(xbits) / 7.0f + 1e-8f;
    float inv_s = 1.0f / s_x;
    float sprod = s_x * g_sw_conv;

    const float* xp = x + b * IN_PIX + (4 * ph) * IN_HW + 4 * pw;  // 16B aligned

    unsigned win[24];
    #pragma unroll
    for (int r = 0; r < 6; r++) {
        float4 v4 = *(const float4*)(xp + r * IN_HW);
        float2 v2 = *(const float2*)(xp + r * IN_HW + 4);
        unsigned p0 = pack4(qcode(v4.x, inv_s), qcode(v4.y, inv_s),
                            qcode(v4.z, inv_s), qcode(v4.w, inv_s));
        unsigned p1 = pack4(qcode(v2.x, inv_s), qcode(v2.y, inv_s), 0, 0);
        win[r * 4 + 0] = p0;
        win[r * 4 + 1] = __funnelshift_r(p0, p1, 8);
        win[r * 4 + 2] = __funnelshift_r(p0, p1, 16);
        win[r * 4 + 3] = __funnelshift_r(p0, p1, 24);
    }

    float* fout = g_flat + b * FLAT_DIM + (ph * 6 + pw) * 16;
    unsigned lmax = 0u;

    #pragma unroll 1
    for (int cg = 0; cg < 4; cg++) {
        float ych[4];
        #pragma unroll
        for (int cc = 0; cc < 4; cc++) {
            int c = cg * 4 + cc;
            int w0 = swp[c * 3 + 0];
            int w1 = swp[c * 3 + 1];
            int w2 = swp[c * 3 + 2];

            int mx = -(1 << 30);
            #pragma unroll
            for (int i = 0; i < 4; i++) {
                #pragma unroll
                for (int j = 0; j < 4; j++) {
                    int acc = __dp4a((int)win[i * 4 + j],       w0, 0);
                    acc     = __dp4a((int)win[(i + 1) * 4 + j], w1, acc);
                    acc     = __dp4a((int)win[(i + 2) * 4 + j], w2, acc);
                    mx = max(mx, acc);
                }
            }
            float y = fmaxf(fmaf((float)mx, sprod, sb[c]), 0.0f);
            ych[cc] = y;
            lmax = max(lmax, __float_as_uint(y));
        }
        *(float4*)(fout + cg * 4) = make_float4(ych[0], ych[1], ych[2], ych[3]);
    }

    lmax = block_umax(lmax, &sm);
    if (threadIdx.x == 0) g_fpart[blockIdx.x] = lmax;
    cudaTriggerProgrammaticLaunchCompletion();
}

// ---------------------------------------------------------------------------
// k_fc: PDL-gated. 2 batch rows per warp, dp4a, redux.sync epilogue.
// ---------------------------------------------------------------------------
__global__ void __launch_bounds__(256)
k_fc(const float* __restrict__ fc_b, float* __restrict__ out) {
    __shared__ int      swq[10 * FC_GROUPS];
    __shared__ float    sbias[10];
    __shared__ unsigned sm;

    int warp = threadIdx.x >> 5;
    int lane = threadIdx.x & 31;
    int b0 = (blockIdx.x * 8 + warp) * 2;

    cudaGridDependencySynchronize();

    unsigned m = 0u;
    for (int i = threadIdx.x; i < CONVBLOCKS; i += 256) m = max(m, g_fpart[i]);
    unsigned fbits = block_umax(m, &sm);

    for (int i = threadIdx.x; i < 10 * FC_GROUPS; i += 256)
        swq[i] = g_fcw_pack[i];
    if (threadIdx.x < 10) sbias[threadIdx.x] = fc_b[threadIdx.x];
    __syncthreads();

    float s_f   = __uint_as_float(fbits) / 7.0f + 1e-8f;
    float inv_s = 1.0f / s_f;
    float sprod = s_f * g_sw_fc;

    const float4* fr0 = (const float4*)(g_flat + b0 * FLAT_DIM);
    const float4* fr1 = (const float4*)(g_flat + (b0 + 1) * FLAT_DIM);

    int acc0[10], acc1[10];
    #pragma unroll
    for (int o = 0; o < 10; o++) { acc0[o] = 0; acc1[o] = 0; }

    #pragma unroll
    for (int it = 0; it < 5; it++) {
        int g = lane + it * 32;
        if (g < FC_GROUPS) {
            float4 v0 = fr0[g];
            float4 v1 = fr1[g];
            int p0 = (int)pack4(
                __float2int_rn(fminf(v0.x * inv_s, 7.0f)),
                __float2int_rn(fminf(v0.y * inv_s, 7.0f)),
                __float2int_rn(fminf(v0.z * inv_s, 7.0f)),
                __float2int_rn(fminf(v0.w * inv_s, 7.0f)));
            int p1 = (int)pack4(
                __float2int_rn(fminf(v1.x * inv_s, 7.0f)),
                __float2int_rn(fminf(v1.y * inv_s, 7.0f)),
                __float2int_rn(fminf(v1.z * inv_s, 7.0f)),
                __float2int_rn(fminf(v1.w * inv_s, 7.0f)));
            #pragma unroll
            for (int o = 0; o < 10; o++) {
                int w = swq[o * FC_GROUPS + g];
                acc0[o] = __dp4a(p0, w, acc0[o]);
                acc1[o] = __dp4a(p1, w, acc1[o]);
            }
        }
    }

    #pragma unroll
    for (int o = 0; o < 10; o++) {
        acc0[o] = __reduce_add_sync(0xFFFFFFFFu, acc0[o]);
        acc1[o] = __reduce_add_sync(0xFFFFFFFFu, acc1[o]);
    }

    if (lane < 10)
        out[b0 * 10 + lane] = fmaf((float)acc0[lane], sprod, sbias[lane]);
    else if (lane >= 16 && lane < 26)
        out[(b0 + 1) * 10 + (lane - 16)] =
            fmaf((float)acc1[lane - 16], sprod, sbias[lane - 16]);
}

// ---------------------------------------------------------------------------
// kernel_launch — graph-capturable; PDL on conv and fc.
// ---------------------------------------------------------------------------
extern "C" void kernel_launch(void* const* d_in, const int* in_sizes, int n_in,
                              void* d_out, int out_size) {
    const float* x      = (const float*)d_in[0];
    const float* conv_w = (const float*)d_in[1];
    const float* conv_b = (const float*)d_in[2];
    const float* fc_w   = (const float*)d_in[3];
    const float* fc_b   = (const float*)d_in[4];
    float* out = (float*)d_out;

    k_amax<<<XBLOCKS + 1, 256>>>(x, conv_w, fc_w);

    cudaLaunchAttribute attr[1];
    attr[0].id = cudaLaunchAttributeProgrammaticStreamSerialization;
    attr[0].val.programmaticStreamSerializationAllowed = 1;

    {
        cudaLaunchConfig_t cfg = {};
        cfg.gridDim  = dim3(CONVBLOCKS);
        cfg.blockDim = dim3(256);
        cfg.attrs    = attr;
        cfg.numAttrs = 1;
        cfg.stream   = 0;
        cudaLaunchKernelEx(&cfg, k_conv, x, conv_b);
    }
    {
        cudaLaunchConfig_t cfg = {};
        cfg.gridDim  = dim3(FCBLOCKS);
        cfg.blockDim = dim3(256);
        cfg.attrs    = attr;
        cfg.numAttrs = 1;
        cfg.stream   = 0;
        cudaLaunchKernelEx(&cfg, k_fc, fc_b, out);
    }
}